// round 1
// baseline (speedup 1.0000x reference)
#include <cuda_runtime.h>
#include <cuda_bf16.h>

// Problem constants (shapes are fixed by the dataset; runtime sizes are
// still read from in_sizes for grid math).
#define E_MAX   250000
#define DIM     64
#define BN_MAX  200000

// Scratch (alloc-free rule: __device__ globals)
__device__ float    g_logits[E_MAX];   // per-edge logit, later overwritten use kept separate
__device__ float    g_ev[E_MAX];       // exp(logit - segmax)
__device__ unsigned g_segmax[E_MAX];   // ordered-uint encoded float max per idx_vi segment
__device__ float    g_segsum[E_MAX];   // sum of exp per idx_vi segment
__device__ float    g_rowsum[64];      // per-batch row sums (B<=64)

// Order-preserving float<->uint encode for atomicMax on floats.
// All finite floats encode to values > 0, so memset-0 is a valid -inf sentinel.
__device__ __forceinline__ unsigned enc_f(float x) {
    unsigned b = __float_as_uint(x);
    return (b & 0x80000000u) ? ~b : (b | 0x80000000u);
}
__device__ __forceinline__ float dec_f(unsigned u) {
    return __uint_as_float((u & 0x80000000u) ? (u & 0x7fffffffu) : ~u);
}

// ---------------------------------------------------------------------------
// K0: zero all scratch + output
// ---------------------------------------------------------------------------
__global__ void k_zero(float* __restrict__ out, int BN, int E) {
    int stride = gridDim.x * blockDim.x;
    int i0 = blockIdx.x * blockDim.x + threadIdx.x;
    for (int i = i0; i < E; i += stride) {
        g_segmax[i] = 0u;
        g_segsum[i] = 0.0f;
    }
    for (int i = i0; i < BN; i += stride) out[i] = 0.0f;
    if (i0 < 64) g_rowsum[i0] = 0.0f;
}

// ---------------------------------------------------------------------------
// K1: warp-per-edge logit computation + segment max (atomicMax)
//   lane owns d = 2*lane, 2*lane+1  -> float2 coalesced gathers (256B/warp/vec)
// ---------------------------------------------------------------------------
__global__ void __launch_bounds__(256)
k_logits(const int*   __restrict__ edges,
         const float* __restrict__ hc,
         const float* __restrict__ hu,
         const float* __restrict__ rel_emb,
         const float* __restrict__ ws,
         const float* __restrict__ bvec,
         const float* __restrict__ out_w,
         const float* __restrict__ out_b,
         int E)
{
    __shared__ float s_ws[8 * DIM];
    __shared__ float s_b[DIM], s_ow[DIM], s_ob[DIM];
    int tid = threadIdx.x;
    for (int i = tid; i < 8 * DIM; i += blockDim.x) s_ws[i] = ws[i];
    for (int i = tid; i < DIM; i += blockDim.x) {
        s_b[i]  = bvec[i];
        s_ow[i] = out_w[i];
        s_ob[i] = out_b[i];
    }
    __syncthreads();

    int gwarp = (blockIdx.x * blockDim.x + tid) >> 5;
    int lane  = tid & 31;
    if (gwarp >= E) return;

    const int* row = edges + (size_t)gwarp * 8;
    int vi   = __ldg(row + 1);
    int vj   = __ldg(row + 2);
    int rel  = __ldg(row + 3);
    int ivi  = __ldg(row + 4);
    int e2vi = __ldg(row + 6);
    int e2vj = __ldg(row + 7);

    int d0 = lane * 2;
    float2 a  = *reinterpret_cast<const float2*>(hc + (size_t)e2vi * DIM + d0);
    float2 c  = *reinterpret_cast<const float2*>(hc + (size_t)e2vj * DIM + d0);
    float2 Au = *reinterpret_cast<const float2*>(hu + (size_t)vi   * DIM + d0);
    float2 Cu = *reinterpret_cast<const float2*>(hu + (size_t)vj   * DIM + d0);
    float2 r  = *reinterpret_cast<const float2*>(rel_emb + (size_t)rel * DIM + d0);

    float av[2] = {a.x, a.y};
    float cv[2] = {c.x, c.y};
    float Av[2] = {Au.x, Au.y};
    float Cv[2] = {Cu.x, Cu.y};
    float rv[2] = {r.x, r.y};

    float acc = 0.0f;
#pragma unroll
    for (int j = 0; j < 2; j++) {
        int d = d0 + j;
        float rr = rv[j];
        float f = s_b[d]
                + av[j] * cv[j] * fmaf(s_ws[1 * DIM + d], rr, s_ws[0 * DIM + d])
                + av[j] * Cv[j] * fmaf(s_ws[3 * DIM + d], rr, s_ws[2 * DIM + d])
                + Av[j] * cv[j] * fmaf(s_ws[5 * DIM + d], rr, s_ws[4 * DIM + d])
                + Av[j] * Cv[j] * fmaf(s_ws[7 * DIM + d], rr, s_ws[6 * DIM + d]);
        acc += fmaxf(f, 0.0f) * s_ow[d] + s_ob[d];
    }

#pragma unroll
    for (int off = 16; off; off >>= 1)
        acc += __shfl_xor_sync(0xffffffffu, acc, off);

    if (lane == 0) {
        g_logits[gwarp] = acc;
        atomicMax(&g_segmax[ivi], enc_f(acc));
    }
}

// ---------------------------------------------------------------------------
// K2: per-edge exp(logit - segmax) + segment sum
// ---------------------------------------------------------------------------
__global__ void k_exp(const int* __restrict__ edges, int E) {
    int e = blockIdx.x * blockDim.x + threadIdx.x;
    if (e >= E) return;
    int ivi = __ldg(edges + (size_t)e * 8 + 4);
    float m = dec_f(g_segmax[ivi]);
    float ev = __expf(g_logits[e] - m);
    g_ev[e] = ev;
    atomicAdd(&g_segsum[ivi], ev);
}

// ---------------------------------------------------------------------------
// K3: per-edge transition -> scatter into new_att[idx, vj]
//   (segment_sum over idx_vj + segment_max of idx/vj + scatter-add collapses
//    to a per-edge atomicAdd because each idx_vj segment has unique (idx,vj))
// ---------------------------------------------------------------------------
__global__ void k_scatter(const int*   __restrict__ edges,
                          const float* __restrict__ na,
                          const float* __restrict__ ey,
                          float*       __restrict__ out,
                          int N, int E)
{
    int e = blockIdx.x * blockDim.x + threadIdx.x;
    if (e >= E) return;
    const int* row = edges + (size_t)e * 8;
    int idx = __ldg(row + 0);
    int vi  = __ldg(row + 1);
    int vj  = __ldg(row + 2);
    int ivi = __ldg(row + 4);
    float tr = g_ev[e] / g_segsum[ivi];
    float ta = __ldg(na + (size_t)idx * N + vi) * tr * __ldg(ey + e);
    atomicAdd(&out[(size_t)idx * N + vj], ta);
}

// ---------------------------------------------------------------------------
// K4: row sums (BLOCKS_PER_ROW blocks per batch row, block reduce + 1 atomic)
// ---------------------------------------------------------------------------
#define BLOCKS_PER_ROW 32
__global__ void k_rowsum(const float* __restrict__ out, int N) {
    __shared__ float sred[256 / 32];
    int b  = blockIdx.x / BLOCKS_PER_ROW;
    int bi = blockIdx.x % BLOCKS_PER_ROW;
    float s = 0.0f;
    for (int i = bi * blockDim.x + threadIdx.x; i < N;
         i += BLOCKS_PER_ROW * blockDim.x)
        s += out[(size_t)b * N + i];
#pragma unroll
    for (int off = 16; off; off >>= 1)
        s += __shfl_xor_sync(0xffffffffu, s, off);
    int lane = threadIdx.x & 31, warp = threadIdx.x >> 5;
    if (lane == 0) sred[warp] = s;
    __syncthreads();
    if (threadIdx.x == 0) {
        float t = 0.0f;
        for (int w = 0; w < (int)(blockDim.x >> 5); w++) t += sred[w];
        atomicAdd(&g_rowsum[b], t);
    }
}

// ---------------------------------------------------------------------------
// K5: normalize
// ---------------------------------------------------------------------------
__global__ void k_norm(float* __restrict__ out, int N, int BN) {
    int i = blockIdx.x * blockDim.x + threadIdx.x;
    if (i >= BN) return;
    out[i] = out[i] / g_rowsum[i / N];
}

// ---------------------------------------------------------------------------
// Launch
// Inputs (metadata order):
//  0 node_attention (B*N f32)   1 selected_edges (E*8 i32)  2 edges_y (E f32)
//  3 hidden_con (n_vis*64 f32)  4 hidden_uncon (N*64 f32)   5 rel_emb (R*64 f32)
//  6 ws (8*64 f32)  7 b (64)  8 out_w (64)  9 out_b (64)
// 10 n_vi_seg (i32 scalar, unused)  11 n_vj_seg (i32 scalar, unused)
// ---------------------------------------------------------------------------
extern "C" void kernel_launch(void* const* d_in, const int* in_sizes, int n_in,
                              void* d_out, int out_size)
{
    const float* na   = (const float*)d_in[0];
    const int*   sel  = (const int*)  d_in[1];
    const float* ey   = (const float*)d_in[2];
    const float* hc   = (const float*)d_in[3];
    const float* hu   = (const float*)d_in[4];
    const float* rel  = (const float*)d_in[5];
    const float* ws   = (const float*)d_in[6];
    const float* bv   = (const float*)d_in[7];
    const float* ow   = (const float*)d_in[8];
    const float* ob   = (const float*)d_in[9];
    float* out = (float*)d_out;

    int E  = in_sizes[2];
    int BN = in_sizes[0];
    int N  = in_sizes[4] / DIM;

    k_zero<<<1024, 256>>>(out, BN, E);

    // warp per edge: 32 threads/edge, 256 threads/block = 8 edges/block
    int blocks1 = (E + 7) / 8;
    k_logits<<<blocks1, 256>>>(sel, hc, hu, rel, ws, bv, ow, ob, E);

    int tb = 256;
    k_exp<<<(E + tb - 1) / tb, tb>>>(sel, E);
    k_scatter<<<(E + tb - 1) / tb, tb>>>(sel, na, ey, out, N, E);

    int B = BN / N;
    k_rowsum<<<B * BLOCKS_PER_ROW, 256>>>(out, N);
    k_norm<<<(BN + tb - 1) / tb, tb>>>(out, N, BN);
}

// round 5
// speedup vs baseline: 1.0310x; 1.0310x over previous
#include <cuda_runtime.h>
#include <cuda_bf16.h>

#define E_MAX   250000
#define DIM     64

// Scratch (alloc-free rule: __device__ globals; total static footprint ~1MB)
__device__ float g_logits[E_MAX];
__device__ float g_rowsum[64];     // per-batch row sums (B<=64)

// ---------------------------------------------------------------------------
// K0: zero output + rowsum scratch
// ---------------------------------------------------------------------------
__global__ void k_zero(float* __restrict__ out, int BN) {
    int stride = gridDim.x * blockDim.x;
    int i0 = blockIdx.x * blockDim.x + threadIdx.x;
    for (int i = i0; i < BN; i += stride) out[i] = 0.0f;
    if (i0 < 64) g_rowsum[i0] = 0.0f;
}

// ---------------------------------------------------------------------------
// K1: logit computation, 16 lanes per edge, float4 gathers (2 edges/warp).
//   lane owns d = 4*lane .. 4*lane+3  -> one 256B wavefront per gathered row.
// ---------------------------------------------------------------------------
__global__ void __launch_bounds__(256)
k_logits(const int*   __restrict__ edges,
         const float* __restrict__ hc,
         const float* __restrict__ hu,
         const float* __restrict__ rel_emb,
         const float* __restrict__ ws,
         const float* __restrict__ bvec,
         const float* __restrict__ out_w,
         const float* __restrict__ out_b,
         int E)
{
    __shared__ float s_ws[8 * DIM];
    __shared__ float s_b[DIM], s_ow[DIM], s_ob[DIM];
    int tid = threadIdx.x;
    for (int i = tid; i < 8 * DIM; i += blockDim.x) s_ws[i] = ws[i];
    for (int i = tid; i < DIM; i += blockDim.x) {
        s_b[i]  = bvec[i];
        s_ow[i] = out_w[i];
        s_ob[i] = out_b[i];
    }
    __syncthreads();

    int gt   = blockIdx.x * blockDim.x + tid;
    int edge = gt >> 4;
    int lane = tid & 15;
    if (edge >= E) return;

    const int* row = edges + (size_t)edge * 8;
    int vi   = __ldg(row + 1);
    int vj   = __ldg(row + 2);
    int rel  = __ldg(row + 3);
    int e2vi = __ldg(row + 6);
    int e2vj = __ldg(row + 7);

    int d0 = lane * 4;
    float4 a  = *reinterpret_cast<const float4*>(hc + (size_t)e2vi * DIM + d0);
    float4 c  = *reinterpret_cast<const float4*>(hc + (size_t)e2vj * DIM + d0);
    float4 Au = *reinterpret_cast<const float4*>(hu + (size_t)vi   * DIM + d0);
    float4 Cu = *reinterpret_cast<const float4*>(hu + (size_t)vj   * DIM + d0);
    float4 r  = *reinterpret_cast<const float4*>(rel_emb + (size_t)rel * DIM + d0);

    float av[4] = {a.x,  a.y,  a.z,  a.w};
    float cv[4] = {c.x,  c.y,  c.z,  c.w};
    float Av[4] = {Au.x, Au.y, Au.z, Au.w};
    float Cv[4] = {Cu.x, Cu.y, Cu.z, Cu.w};
    float rv[4] = {r.x,  r.y,  r.z,  r.w};

    float acc = 0.0f;
#pragma unroll
    for (int j = 0; j < 4; j++) {
        int d = d0 + j;
        float rr = rv[j];
        float f = s_b[d]
                + av[j] * cv[j] * fmaf(s_ws[1 * DIM + d], rr, s_ws[0 * DIM + d])
                + av[j] * Cv[j] * fmaf(s_ws[3 * DIM + d], rr, s_ws[2 * DIM + d])
                + Av[j] * cv[j] * fmaf(s_ws[5 * DIM + d], rr, s_ws[4 * DIM + d])
                + Av[j] * Cv[j] * fmaf(s_ws[7 * DIM + d], rr, s_ws[6 * DIM + d]);
        acc += fmaxf(f, 0.0f) * s_ow[d] + s_ob[d];
    }

    // reduce across the 16-lane group (offsets stay within the half-warp)
#pragma unroll
    for (int off = 8; off; off >>= 1)
        acc += __shfl_xor_sync(0xffffffffu, acc, off);

    if (lane == 0) g_logits[edge] = acc;
}

// ---------------------------------------------------------------------------
// K2: fused segment softmax + scatter + rowsum.
//   Edges are lexsorted by (idx, vi, vj), and idx_vi is the unique-id of
//   (idx, vi) -> every softmax segment is a CONTIGUOUS run. A thread that
//   lands on a run start processes the whole (short, avg 1.75-edge) run:
//   max, sum of exp, then ta = na*exp/sum*ey scattered with one atomicAdd
//   per edge. Row sums accumulate via warp-aggregated atomics (idx sorted
//   -> uniform within nearly every warp).
// ---------------------------------------------------------------------------
__global__ void __launch_bounds__(256)
k_softmax_scatter(const int*   __restrict__ edges,
                  const float* __restrict__ na,
                  const float* __restrict__ ey,
                  float*       __restrict__ out,
                  int N, int E)
{
    int e  = blockIdx.x * blockDim.x + threadIdx.x;
    int ec = min(e, E - 1);
    const int* row = edges + (size_t)ec * 8;
    int idx = __ldg(row + 0);

    float tasum = 0.0f;
    if (e < E) {
        int ivi = __ldg(row + 4);
        bool start = (e == 0) || (__ldg(row - 8 + 4) != ivi);
        if (start) {
            // scan run extent + max
            float m = -1e30f;
            int L = 0;
            for (int k = e; k < E; k++) {
                if (k > e && __ldg(edges + (size_t)k * 8 + 4) != ivi) break;
                m = fmaxf(m, g_logits[k]);
                L++;
            }
            float s = 0.0f;
            for (int k = e; k < e + L; k++)
                s += __expf(g_logits[k] - m);

            int   vi   = __ldg(row + 1);
            float coef = __ldg(na + (size_t)idx * N + vi) / s;

            for (int k = e; k < e + L; k++) {
                float ta = coef * __expf(g_logits[k] - m) * __ldg(ey + k);
                int vj = __ldg(edges + (size_t)k * 8 + 2);
                atomicAdd(&out[(size_t)idx * N + vj], ta);
                tasum += ta;
            }
        }
    }

    // warp-aggregated rowsum atomics (idx uniform within warp except at the
    // 3 batch boundaries in the whole edge list)
    int idx0 = __shfl_sync(0xffffffffu, idx, 0);
    bool uni = __all_sync(0xffffffffu, idx == idx0);
    if (uni) {
        float w = tasum;
#pragma unroll
        for (int off = 16; off; off >>= 1)
            w += __shfl_xor_sync(0xffffffffu, w, off);
        if ((threadIdx.x & 31) == 0 && w != 0.0f)
            atomicAdd(&g_rowsum[idx0], w);
    } else if (tasum != 0.0f) {
        atomicAdd(&g_rowsum[idx], tasum);
    }
}

// ---------------------------------------------------------------------------
// K3: normalize rows
// ---------------------------------------------------------------------------
__global__ void k_norm(float* __restrict__ out, int N, int BN) {
    int i = blockIdx.x * blockDim.x + threadIdx.x;
    if (i >= BN) return;
    out[i] = out[i] / g_rowsum[i / N];
}

// ---------------------------------------------------------------------------
// Inputs (metadata order):
//  0 node_attention (B*N f32)   1 selected_edges (E*8 i32)  2 edges_y (E f32)
//  3 hidden_con (n_vis*64 f32)  4 hidden_uncon (N*64 f32)   5 rel_emb (R*64 f32)
//  6 ws (8*64 f32)  7 b (64)  8 out_w (64)  9 out_b (64)
// ---------------------------------------------------------------------------
extern "C" void kernel_launch(void* const* d_in, const int* in_sizes, int n_in,
                              void* d_out, int out_size)
{
    const float* na   = (const float*)d_in[0];
    const int*   sel  = (const int*)  d_in[1];
    const float* ey   = (const float*)d_in[2];
    const float* hc   = (const float*)d_in[3];
    const float* hu   = (const float*)d_in[4];
    const float* rel  = (const float*)d_in[5];
    const float* ws   = (const float*)d_in[6];
    const float* bv   = (const float*)d_in[7];
    const float* ow   = (const float*)d_in[8];
    const float* ob   = (const float*)d_in[9];
    float* out = (float*)d_out;

    int E  = in_sizes[2];
    int BN = in_sizes[0];
    int N  = in_sizes[4] / DIM;

    k_zero<<<512, 256>>>(out, BN);

    // 16 threads per edge, 256 threads/block = 16 edges/block
    int blocks1 = (E * 16 + 255) / 256;
    k_logits<<<blocks1, 256>>>(sel, hc, hu, rel, ws, bv, ow, ob, E);

    int tb = 256;
    k_softmax_scatter<<<(E + tb - 1) / tb, tb>>>(sel, na, ey, out, N, E);
    k_norm<<<(BN + tb - 1) / tb, tb>>>(out, N, BN);
}